// round 14
// baseline (speedup 1.0000x reference)
#include <cuda_runtime.h>
#include <cstdint>

// Furthest Point Sampling, exact-match to JAX reference.
// B=16, N=32768, M=2048. One 8-CTA cluster per batch; 4096 pts/CTA in
// f32x2-packed registers across 128 threads (32 pts/thread). FLAT exchange
// (R11 structure): each of the 4 warps pushes its warp candidate to all 8
// CTAs via two st.async messages carrying mbarrier complete_tx: b64 key +
// v2.b64 {xy, z}. Single transaction barrier per buffer. This round:
// DENSE key array (8B stride -> conflict-free 32-lane key LDS; R11's 32B
// slot stride was an 8-way bank conflict) and the expect_tx re-arm moved
// off the critical path (after seed extraction). Negated coords, LDS.128
// fetches, fused update+pair-max, hierarchical first-index scan.

constexpr int NPTS = 32768;
constexpr int MOUT = 2048;
constexpr int CS   = 8;            // cluster size (CTAs per batch)
constexpr int PCTA = NPTS / CS;    // 4096 points per CTA
constexpr int NT   = 128;          // threads per CTA
constexpr int PPT  = PCTA / NT;    // 32 points per thread
constexpr int NPAIR = PPT / 2;     // 16 packed pairs per thread
constexpr int NW   = NT / 32;      // 4 warps
constexpr int NSLOT = CS * NW;     // 32 candidate slots
constexpr unsigned TXB = (unsigned)NSLOT * 24u;  // 768 B per phase (8+16)

struct __align__(16) CSlot {               // 16B coord slot (one v2.b64 msg)
    unsigned long long xy;
    unsigned long long z;
};

struct __align__(16) ClusterShm {
    unsigned long long mbar[2];            // transaction barriers (dbl-buffered)
    unsigned long long skey[2][NSLOT];     // DENSE keys: 8B stride, no conflict
    CSlot              scrd[2][NSLOT];     // {xy, z} coord slots
    float4             cxyz[PCTA];         // NEGATED coords {-x,-y,-z,0}
};

__device__ __forceinline__ uint32_t smem_u32(const void* p) {
    return (uint32_t)__cvta_generic_to_shared(p);
}
__device__ __forceinline__ uint32_t mapa_u32(uint32_t a, uint32_t r) {
    uint32_t out;
    asm("mapa.shared::cluster.u32 %0, %1, %2;" : "=r"(out) : "r"(a), "r"(r));
    return out;
}
// HW-sleep transaction-barrier wait (suspendTime hint -> nap, not hot spin).
__device__ __forceinline__ void mbar_wait_sleep(uint32_t addr, uint32_t parity) {
    asm volatile(
        "{\n\t"
        ".reg .pred P;\n\t"
        "WAITLOOP%=:\n\t"
        "mbarrier.try_wait.parity.acquire.cta.shared::cta.b64 P, [%0], %1, 0x989680;\n\t"
        "@!P bra WAITLOOP%=;\n\t"
        "}"
        :: "r"(addr), "r"(parity) : "memory");
}
__device__ __forceinline__ unsigned long long pack2(float lo, float hi) {
    unsigned long long r;
    asm("mov.b64 %0, {%1, %2};" : "=l"(r) : "f"(lo), "f"(hi));
    return r;
}
__device__ __forceinline__ void unpack2(unsigned long long v, float& lo, float& hi) {
    asm("mov.b64 {%0, %1}, %2;" : "=f"(lo), "=f"(hi) : "l"(v));
}
__device__ __forceinline__ unsigned long long addx2(unsigned long long a, unsigned long long b) {
    unsigned long long r;
    asm("add.rn.f32x2 %0, %1, %2;" : "=l"(r) : "l"(a), "l"(b));
    return r;
}
__device__ __forceinline__ unsigned long long mulx2(unsigned long long a, unsigned long long b) {
    unsigned long long r;
    asm("mul.rn.f32x2 %0, %1, %2;" : "=l"(r) : "l"(a), "l"(b));
    return r;
}
__device__ __forceinline__ float negf(float v) {         // exact sign flip
    return __uint_as_float(__float_as_uint(v) ^ 0x80000000u);
}

__global__ void __launch_bounds__(NT, 1) __cluster_dims__(CS, 1, 1)
fps_kernel(const float* __restrict__ pts, float* __restrict__ out)
{
    extern __shared__ __align__(16) char shm_raw[];
    ClusterShm* s = reinterpret_cast<ClusterShm*>(shm_raw);

    const int tid = threadIdx.x;
    uint32_t rank;
    asm("mov.u32 %0, %%cluster_ctarank;" : "=r"(rank));
    const int batch = blockIdx.x / CS;

    const float* px = pts + (size_t)batch * 3u * NPTS;
    const float* py = px + NPTS;
    const float* pz = px + 2 * NPTS;
    float* ob = out + (size_t)batch * 3u * MOUT;

    const uint32_t mb0 = smem_u32(&s->mbar[0]);
    const uint32_t mb1 = smem_u32(&s->mbar[1]);
    if (tid == 0) {
        asm volatile("mbarrier.init.shared.b64 [%0], 1;" :: "r"(mb0) : "memory");
        asm volatile("mbarrier.init.shared.b64 [%0], 1;" :: "r"(mb1) : "memory");
        // Arm both buffers for their first phase.
        asm volatile("mbarrier.arrive.expect_tx.shared.b64 _, [%0], %1;"
                     :: "r"(mb0), "r"(TXB) : "memory");
        asm volatile("mbarrier.arrive.expect_tx.shared.b64 _, [%0], %1;"
                     :: "r"(mb1), "r"(TXB) : "memory");
    }

    // Load this CTA's 4096 points into packed registers (+ NEGATED float4
    // smem copy for winner lookup / transmission).
    unsigned long long X2[NPAIR], Y2[NPAIR], Z2[NPAIR];
    float d[PPT];
    const int base = (int)rank * PCTA + tid;   // global point index, k-strided
#pragma unroll
    for (int p = 0; p < NPAIR; ++p) {
        const int n0 = base + (2 * p) * NT;        // coalesced
        const int n1 = base + (2 * p + 1) * NT;
        float x0 = px[n0], x1 = px[n1];
        float y0 = py[n0], y1 = py[n1];
        float z0 = pz[n0], z1 = pz[n1];
        X2[p] = pack2(x0, x1);
        Y2[p] = pack2(y0, y1);
        Z2[p] = pack2(z0, z1);
        d[2 * p] = 1e10f; d[2 * p + 1] = 1e10f;
        const int l0 = tid + (2 * p) * NT;
        const int l1 = tid + (2 * p + 1) * NT;
        s->cxyz[l0] = make_float4(negf(x0), negf(y0), negf(z0), 0.0f);
        s->cxyz[l1] = make_float4(negf(x1), negf(y1), negf(z1), 0.0f);
    }
    // Seed 0 = global point 0 (CUDA FPS convention). State held NEGATED.
    float nlx = negf(px[0]), nly = negf(py[0]), nlz = negf(pz[0]);

    __syncthreads();
    // Barriers armed cluster-wide before any peer st.async can land.
    asm volatile("barrier.cluster.arrive.aligned;" ::: "memory");
    asm volatile("barrier.cluster.wait.aligned;"   ::: "memory");

    const bool writer = (rank == 0u) && (tid == 0);
    const int lane = tid & 31;
    const int wid  = tid >> 5;

    // Hoisted remote addresses: this warp's slot (rank*NW + wid) in target
    // CTA (lane & 7), plus the target's transaction barrier.
    const uint32_t tr = (uint32_t)(lane & 7);
    const int myslot = (int)rank * NW + wid;
    uint32_t a_k[2], a_xz[2], a_mb[2];
#pragma unroll
    for (int b = 0; b < 2; ++b) {
        a_k[b]  = mapa_u32(smem_u32(&s->skey[b][myslot]),    tr);
        a_xz[b] = mapa_u32(smem_u32(&s->scrd[b][myslot].xy), tr);
        a_mb[b] = mapa_u32(b == 0 ? mb0 : mb1, tr);
    }

    for (int j = 0; j < MOUT; ++j) {
        // Emit current selection (un-negate; this IS the gathered output).
        if (writer) {
            ob[j] = negf(nlx); ob[MOUT + j] = negf(nly); ob[2 * MOUT + j] = negf(nlz);
        }
        if (j == MOUT - 1) break;

        // --- packed distance update, fused with pair-max.
        //     Exact fp32 rn: (dx^2+dy^2)+dz^2, dx = x + (-sx). ---
        const unsigned long long nlx2 = pack2(nlx, nlx);
        const unsigned long long nly2 = pack2(nly, nly);
        const unsigned long long nlz2 = pack2(nlz, nlz);
        float m16[NPAIR];
#pragma unroll
        for (int p = 0; p < NPAIR; ++p) {
            unsigned long long dx = addx2(X2[p], nlx2);
            unsigned long long dy = addx2(Y2[p], nly2);
            unsigned long long dz = addx2(Z2[p], nlz2);
            unsigned long long dd = addx2(addx2(mulx2(dx, dx), mulx2(dy, dy)),
                                          mulx2(dz, dz));
            float f0, f1; unpack2(dd, f0, f1);
            d[2 * p]     = fminf(d[2 * p],     f0);
            d[2 * p + 1] = fminf(d[2 * p + 1], f1);
            m16[p] = fmaxf(d[2 * p], d[2 * p + 1]);
        }
        // --- per-thread argmax: shallow tree + hierarchical first-index ---
        float m8[8];
#pragma unroll
        for (int i = 0; i < 8; ++i) m8[i] = fmaxf(m16[2 * i], m16[2 * i + 1]);
        float m4a = fmaxf(m8[0], m8[1]), m4b = fmaxf(m8[2], m8[3]);
        float m4c = fmaxf(m8[4], m8[5]), m4d = fmaxf(m8[6], m8[7]);
        const float bv = fmaxf(fmaxf(m4a, m4b), fmaxf(m4c, m4d));
        // First pair-group whose max equals bv holds the first k with d==bv.
        uint32_t gmsk = 0;
#pragma unroll
        for (int i = 0; i < NPAIR; ++i) gmsk |= (m16[i] == bv) ? (1u << i) : 0u;
        const int gi = __ffs(gmsk) - 1;
        const int bk = 2 * gi + ((d[2 * gi] == bv) ? 0 : 1);
        const int bgidx = base + bk * NT;      // gidx increases with k

        // --- warp argmax via redux.sync (dist >= 0: bits order-preserving) ---
        const uint32_t bvbits = __float_as_uint(bv);
        const uint32_t wval = __reduce_max_sync(0xFFFFFFFFu, bvbits);
        const uint32_t cand = (bvbits == wval) ? (uint32_t)bgidx : 0xFFFFFFFFu;
        const uint32_t widx = __reduce_min_sync(0xFFFFFFFFu, cand);

        // --- warp-winner NEGATED coords: one broadcast LDS.128 ---
        const int lidx = (int)widx - (int)rank * PCTA;       // CTA-local
        const float4 wc = s->cxyz[lidx];
        const unsigned long long ck =
            ((unsigned long long)wval << 32) |
            (unsigned long long)(0xFFFFFFFFu - widx);
        const unsigned long long cxy = pack2(wc.x, wc.y);
        const unsigned long long cz  = pack2(wc.z, 0.0f);

        const int buf = j & 1;
        const uint32_t parity = (uint32_t)(j >> 1) & 1u;

        // --- lanes 0..7: push this warp's candidate to every CTA.
        //     b64 key + v2.b64 {xy, z}, each carrying complete_tx at the
        //     TARGET's barrier: 64 update events per barrier per phase. ---
        asm volatile(
            "{\n\t"
            ".reg .pred p;\n\t"
            "setp.lt.u32 p, %0, 8;\n\t"
            "@p st.async.shared::cluster.mbarrier::complete_tx::bytes.b64 [%1], %3, [%2];\n\t"
            "@p st.async.shared::cluster.mbarrier::complete_tx::bytes.v2.b64 [%4], {%5, %6}, [%2];\n\t"
            "}"
            :: "r"((uint32_t)lane), "r"(a_k[buf]), "r"(a_mb[buf]),
               "l"(ck), "r"(a_xz[buf]), "l"(cxy), "l"(cz)
            : "memory");

        // --- sleep-wait for all 768 bytes (8 CTAs x 4 warps x 24B) ---
        mbar_wait_sleep(buf ? mb1 : mb0, parity);

        // --- 32-candidate reduce: 1 conflict-free key LDS + two redux ---
        const unsigned long long m = s->skey[buf][lane];
        const uint32_t mv = (uint32_t)(m >> 32);
        const uint32_t gv = __reduce_max_sync(0xFFFFFFFFu, mv);
        const uint32_t inv = (mv == gv) ? (uint32_t)m : 0u;   // ~g, >0 always
        const uint32_t ginv = __reduce_max_sync(0xFFFFFFFFu, inv);
        const uint32_t g = 0xFFFFFFFFu - ginv;                // winning gidx
        // Winner's slot: src CTA = g / PCTA, src warp = (g % NT) / 32.
        const int wslot = (int)(g >> 12) * NW + (int)((g & (NT - 1)) >> 5);
        // One broadcast LDS.128: {xy, z}.
        unsigned long long wxy, wz;
        asm volatile("ld.shared.v2.u64 {%0, %1}, [%2];"
                     : "=l"(wxy), "=l"(wz)
                     : "r"(smem_u32(&s->scrd[buf][wslot].xy)));
        float zlo, zhi;
        unpack2(wxy, nlx, nly);
        unpack2(wz, zlo, zhi);
        nlz = zlo;

        // Re-arm this buffer for phase j+2 — AFTER seed extraction, off the
        // critical chain. Causally safe: any j+2 message requires the sender
        // to have observed phase j+1 complete, which requires OUR j+1 sends,
        // which are issued after this re-arm in warp 0's program order.
        if (tid == 0) {
            asm volatile("mbarrier.arrive.expect_tx.shared.b64 _, [%0], %1;"
                         :: "r"(buf ? mb1 : mb0), "r"(TXB) : "memory");
        }
        // Slot WAR across phases: our reads precede our own j+1 sends
        // (program order per warp); any peer j+2 store requires all 32 j+1
        // messages, hence follows every warp's reads of buffer `buf`.
    }

    // No CTA exits while peers may still be touching its SMEM.
    asm volatile("barrier.cluster.arrive.aligned;" ::: "memory");
    asm volatile("barrier.cluster.wait.aligned;"   ::: "memory");
}

extern "C" void kernel_launch(void* const* d_in, const int* in_sizes, int n_in,
                              void* d_out, int out_size)
{
    (void)n_in; (void)out_size;
    const float* pts = (const float*)d_in[0];
    float* out = (float*)d_out;
    const int B = in_sizes[0] / (3 * NPTS);   // 16

    const size_t shm = sizeof(ClusterShm);    // ~66 KB
    cudaFuncSetAttribute(fps_kernel, cudaFuncAttributeMaxDynamicSharedMemorySize,
                         (int)shm);
    fps_kernel<<<B * CS, NT, shm>>>(pts, out);
}

// round 15
// speedup vs baseline: 1.6222x; 1.6222x over previous
#include <cuda_runtime.h>
#include <cstdint>

// Furthest Point Sampling, exact-match to JAX reference.
// B=16, N=32768, M=2048. One 8-CTA cluster per batch; 4096 pts/CTA in
// f32x2-packed registers across 128 threads (32 pts/thread). FLAT exchange
// (R11 structure, PROVEN): each of the 4 warps pushes its warp candidate to
// all 8 CTAs via two st.async messages carrying mbarrier complete_tx:
// b64 key + v2.b64 {xy, z}, into 32B SECTOR-EXCLUSIVE slots (one remote
// writer per 32B sector — R13 showed shared sectors serialize remote
// stores expensively). Single transaction barrier per buffer, re-arm right
// after the wait. THIS ROUND: output emission moved into the flight shadow
// (after send, before wait) so warp 0's STGs leave the gating chain.

constexpr int NPTS = 32768;
constexpr int MOUT = 2048;
constexpr int CS   = 8;            // cluster size (CTAs per batch)
constexpr int PCTA = NPTS / CS;    // 4096 points per CTA
constexpr int NT   = 128;          // threads per CTA
constexpr int PPT  = PCTA / NT;    // 32 points per thread
constexpr int NPAIR = PPT / 2;     // 16 packed pairs per thread
constexpr int NW   = NT / 32;      // 4 warps
constexpr int NSLOT = CS * NW;     // 32 candidate slots
constexpr unsigned TXB = (unsigned)NSLOT * 24u;  // 768 B per phase (8+16)

struct __align__(32) KSlot {               // 32B sector-exclusive slot
    unsigned long long key;                // +0   (msg1: b64)
    unsigned long long pad;
    unsigned long long xy;                 // +16  (msg2: v2.b64 {xy, z})
    unsigned long long z;                  // +24
};

struct __align__(16) ClusterShm {
    unsigned long long mbar[2];            // transaction barriers (dbl-buffered)
    KSlot              skv[2][NSLOT];      // candidate slots [buf][src slot]
    float4             cxyz[PCTA];         // NEGATED coords {-x,-y,-z,0}
};

__device__ __forceinline__ uint32_t smem_u32(const void* p) {
    return (uint32_t)__cvta_generic_to_shared(p);
}
__device__ __forceinline__ uint32_t mapa_u32(uint32_t a, uint32_t r) {
    uint32_t out;
    asm("mapa.shared::cluster.u32 %0, %1, %2;" : "=r"(out) : "r"(a), "r"(r));
    return out;
}
// HW-sleep transaction-barrier wait (suspendTime hint -> nap, not hot spin).
__device__ __forceinline__ void mbar_wait_sleep(uint32_t addr, uint32_t parity) {
    asm volatile(
        "{\n\t"
        ".reg .pred P;\n\t"
        "WAITLOOP%=:\n\t"
        "mbarrier.try_wait.parity.acquire.cta.shared::cta.b64 P, [%0], %1, 0x989680;\n\t"
        "@!P bra WAITLOOP%=;\n\t"
        "}"
        :: "r"(addr), "r"(parity) : "memory");
}
__device__ __forceinline__ unsigned long long pack2(float lo, float hi) {
    unsigned long long r;
    asm("mov.b64 %0, {%1, %2};" : "=l"(r) : "f"(lo), "f"(hi));
    return r;
}
__device__ __forceinline__ void unpack2(unsigned long long v, float& lo, float& hi) {
    asm("mov.b64 {%0, %1}, %2;" : "=f"(lo), "=f"(hi) : "l"(v));
}
__device__ __forceinline__ unsigned long long addx2(unsigned long long a, unsigned long long b) {
    unsigned long long r;
    asm("add.rn.f32x2 %0, %1, %2;" : "=l"(r) : "l"(a), "l"(b));
    return r;
}
__device__ __forceinline__ unsigned long long mulx2(unsigned long long a, unsigned long long b) {
    unsigned long long r;
    asm("mul.rn.f32x2 %0, %1, %2;" : "=l"(r) : "l"(a), "l"(b));
    return r;
}
__device__ __forceinline__ float negf(float v) {         // exact sign flip
    return __uint_as_float(__float_as_uint(v) ^ 0x80000000u);
}

__global__ void __launch_bounds__(NT, 1) __cluster_dims__(CS, 1, 1)
fps_kernel(const float* __restrict__ pts, float* __restrict__ out)
{
    extern __shared__ __align__(16) char shm_raw[];
    ClusterShm* s = reinterpret_cast<ClusterShm*>(shm_raw);

    const int tid = threadIdx.x;
    uint32_t rank;
    asm("mov.u32 %0, %%cluster_ctarank;" : "=r"(rank));
    const int batch = blockIdx.x / CS;

    const float* px = pts + (size_t)batch * 3u * NPTS;
    const float* py = px + NPTS;
    const float* pz = px + 2 * NPTS;
    float* ob = out + (size_t)batch * 3u * MOUT;

    const uint32_t mb0 = smem_u32(&s->mbar[0]);
    const uint32_t mb1 = smem_u32(&s->mbar[1]);
    if (tid == 0) {
        asm volatile("mbarrier.init.shared.b64 [%0], 1;" :: "r"(mb0) : "memory");
        asm volatile("mbarrier.init.shared.b64 [%0], 1;" :: "r"(mb1) : "memory");
        // Arm both buffers for their first phase.
        asm volatile("mbarrier.arrive.expect_tx.shared.b64 _, [%0], %1;"
                     :: "r"(mb0), "r"(TXB) : "memory");
        asm volatile("mbarrier.arrive.expect_tx.shared.b64 _, [%0], %1;"
                     :: "r"(mb1), "r"(TXB) : "memory");
    }

    // Load this CTA's 4096 points into packed registers (+ NEGATED float4
    // smem copy for winner lookup / transmission).
    unsigned long long X2[NPAIR], Y2[NPAIR], Z2[NPAIR];
    float d[PPT];
    const int base = (int)rank * PCTA + tid;   // global point index, k-strided
#pragma unroll
    for (int p = 0; p < NPAIR; ++p) {
        const int n0 = base + (2 * p) * NT;        // coalesced
        const int n1 = base + (2 * p + 1) * NT;
        float x0 = px[n0], x1 = px[n1];
        float y0 = py[n0], y1 = py[n1];
        float z0 = pz[n0], z1 = pz[n1];
        X2[p] = pack2(x0, x1);
        Y2[p] = pack2(y0, y1);
        Z2[p] = pack2(z0, z1);
        d[2 * p] = 1e10f; d[2 * p + 1] = 1e10f;
        const int l0 = tid + (2 * p) * NT;
        const int l1 = tid + (2 * p + 1) * NT;
        s->cxyz[l0] = make_float4(negf(x0), negf(y0), negf(z0), 0.0f);
        s->cxyz[l1] = make_float4(negf(x1), negf(y1), negf(z1), 0.0f);
    }
    // Seed 0 = global point 0 (CUDA FPS convention). State held NEGATED.
    float nlx = negf(px[0]), nly = negf(py[0]), nlz = negf(pz[0]);

    __syncthreads();
    // Barriers armed cluster-wide before any peer st.async can land.
    asm volatile("barrier.cluster.arrive.aligned;" ::: "memory");
    asm volatile("barrier.cluster.wait.aligned;"   ::: "memory");

    const bool writer = (rank == 0u) && (tid == 0);
    const int lane = tid & 31;
    const int wid  = tid >> 5;

    // Hoisted remote addresses: this warp's slot (rank*NW + wid) in target
    // CTA (lane & 7), plus the target's transaction barrier.
    const uint32_t tr = (uint32_t)(lane & 7);
    const int myslot = (int)rank * NW + wid;
    uint32_t a_k[2], a_xz[2], a_mb[2];
#pragma unroll
    for (int b = 0; b < 2; ++b) {
        a_k[b]  = mapa_u32(smem_u32(&s->skv[b][myslot].key), tr);
        a_xz[b] = mapa_u32(smem_u32(&s->skv[b][myslot].xy),  tr);
        a_mb[b] = mapa_u32(b == 0 ? mb0 : mb1, tr);
    }

    for (int j = 0; j < MOUT - 1; ++j) {
        // --- packed distance update with seed j, fused with pair-max.
        //     Exact fp32 rn: (dx^2+dy^2)+dz^2, dx = x + (-sx). ---
        const unsigned long long nlx2 = pack2(nlx, nlx);
        const unsigned long long nly2 = pack2(nly, nly);
        const unsigned long long nlz2 = pack2(nlz, nlz);
        float m16[NPAIR];
#pragma unroll
        for (int p = 0; p < NPAIR; ++p) {
            unsigned long long dx = addx2(X2[p], nlx2);
            unsigned long long dy = addx2(Y2[p], nly2);
            unsigned long long dz = addx2(Z2[p], nlz2);
            unsigned long long dd = addx2(addx2(mulx2(dx, dx), mulx2(dy, dy)),
                                          mulx2(dz, dz));
            float f0, f1; unpack2(dd, f0, f1);
            d[2 * p]     = fminf(d[2 * p],     f0);
            d[2 * p + 1] = fminf(d[2 * p + 1], f1);
            m16[p] = fmaxf(d[2 * p], d[2 * p + 1]);
        }
        // --- per-thread argmax: shallow tree + hierarchical first-index ---
        float m8[8];
#pragma unroll
        for (int i = 0; i < 8; ++i) m8[i] = fmaxf(m16[2 * i], m16[2 * i + 1]);
        float m4a = fmaxf(m8[0], m8[1]), m4b = fmaxf(m8[2], m8[3]);
        float m4c = fmaxf(m8[4], m8[5]), m4d = fmaxf(m8[6], m8[7]);
        const float bv = fmaxf(fmaxf(m4a, m4b), fmaxf(m4c, m4d));
        // First pair-group whose max equals bv holds the first k with d==bv.
        uint32_t gmsk = 0;
#pragma unroll
        for (int i = 0; i < NPAIR; ++i) gmsk |= (m16[i] == bv) ? (1u << i) : 0u;
        const int gi = __ffs(gmsk) - 1;
        const int bk = 2 * gi + ((d[2 * gi] == bv) ? 0 : 1);
        const int bgidx = base + bk * NT;      // gidx increases with k

        // --- warp argmax via redux.sync (dist >= 0: bits order-preserving) ---
        const uint32_t bvbits = __float_as_uint(bv);
        const uint32_t wval = __reduce_max_sync(0xFFFFFFFFu, bvbits);
        const uint32_t cand = (bvbits == wval) ? (uint32_t)bgidx : 0xFFFFFFFFu;
        const uint32_t widx = __reduce_min_sync(0xFFFFFFFFu, cand);

        // --- warp-winner NEGATED coords: one broadcast LDS.128 ---
        const int lidx = (int)widx - (int)rank * PCTA;       // CTA-local
        const float4 wc = s->cxyz[lidx];
        const unsigned long long ck =
            ((unsigned long long)wval << 32) |
            (unsigned long long)(0xFFFFFFFFu - widx);
        const unsigned long long cxy = pack2(wc.x, wc.y);
        const unsigned long long cz  = pack2(wc.z, 0.0f);

        const int buf = j & 1;
        const uint32_t parity = (uint32_t)(j >> 1) & 1u;

        // --- lanes 0..7: push this warp's candidate to every CTA.
        //     b64 key + v2.b64 {xy, z}, each carrying complete_tx at the
        //     TARGET's barrier: 64 update events per barrier per phase. ---
        asm volatile(
            "{\n\t"
            ".reg .pred p;\n\t"
            "setp.lt.u32 p, %0, 8;\n\t"
            "@p st.async.shared::cluster.mbarrier::complete_tx::bytes.b64 [%1], %3, [%2];\n\t"
            "@p st.async.shared::cluster.mbarrier::complete_tx::bytes.v2.b64 [%4], {%5, %6}, [%2];\n\t"
            "}"
            :: "r"((uint32_t)lane), "r"(a_k[buf]), "r"(a_mb[buf]),
               "l"(ck), "r"(a_xz[buf]), "l"(cxy), "l"(cz)
            : "memory");

        // --- emit selection j INSIDE the flight shadow (un-negate) ---
        if (writer) {
            ob[j] = negf(nlx); ob[MOUT + j] = negf(nly); ob[2 * MOUT + j] = negf(nlz);
        }

        // --- sleep-wait for all 768 bytes (8 CTAs x 4 warps x 24B) ---
        mbar_wait_sleep(buf ? mb1 : mb0, parity);

        // Re-arm this buffer for phase j+2. Causally safe: any j+2 message
        // requires the sender to have completed phase j+1, which requires
        // OUR j+1 sends, which are issued after this re-arm.
        if (tid == 0) {
            asm volatile("mbarrier.arrive.expect_tx.shared.b64 _, [%0], %1;"
                         :: "r"(buf ? mb1 : mb0), "r"(TXB) : "memory");
        }

        // --- 32-candidate reduce: 1 key/lane + two redux ops ---
        const unsigned long long m = s->skv[buf][lane].key;
        const uint32_t mv = (uint32_t)(m >> 32);
        const uint32_t gv = __reduce_max_sync(0xFFFFFFFFu, mv);
        const uint32_t inv = (mv == gv) ? (uint32_t)m : 0u;   // ~g, >0 always
        const uint32_t ginv = __reduce_max_sync(0xFFFFFFFFu, inv);
        const uint32_t g = 0xFFFFFFFFu - ginv;                // winning gidx
        // Winner's slot: src CTA = g / PCTA, src warp = (g % NT) / 32.
        const int wslot = (int)(g >> 12) * NW + (int)((g & (NT - 1)) >> 5);
        // One broadcast LDS.128: {xy, z} at slot+16.
        unsigned long long wxy, wz;
        asm volatile("ld.shared.v2.u64 {%0, %1}, [%2];"
                     : "=l"(wxy), "=l"(wz)
                     : "r"(smem_u32(&s->skv[buf][wslot].xy)));
        float zlo, zhi;
        unpack2(wxy, nlx, nly);
        unpack2(wz, zlo, zhi);
        nlz = zlo;
        // Slot WAR across phases: our reads precede our own j+1 sends
        // (program order per warp); any peer j+2 store requires all 32 j+1
        // messages, hence follows every warp's reads of buffer `buf`.
    }

    // Final selection (j = MOUT-1).
    if (writer) {
        ob[MOUT - 1] = negf(nlx);
        ob[2 * MOUT - 1] = negf(nly);
        ob[3 * MOUT - 1] = negf(nlz);
    }

    // No CTA exits while peers may still be touching its SMEM.
    asm volatile("barrier.cluster.arrive.aligned;" ::: "memory");
    asm volatile("barrier.cluster.wait.aligned;"   ::: "memory");
}

extern "C" void kernel_launch(void* const* d_in, const int* in_sizes, int n_in,
                              void* d_out, int out_size)
{
    (void)n_in; (void)out_size;
    const float* pts = (const float*)d_in[0];
    float* out = (float*)d_out;
    const int B = in_sizes[0] / (3 * NPTS);   // 16

    const size_t shm = sizeof(ClusterShm);    // ~67 KB
    cudaFuncSetAttribute(fps_kernel, cudaFuncAttributeMaxDynamicSharedMemorySize,
                         (int)shm);
    fps_kernel<<<B * CS, NT, shm>>>(pts, out);
}